// round 8
// baseline (speedup 1.0000x reference)
#include <cuda_runtime.h>

#define NPIX   (480*480)
#define NCLS   124
#define FCH    64
#define IN_HW  120
#define EPS_F  1e-8f
#define GRID   296        // 148 SMs x 2 co-resident blocks (<=128 regs) -- barrier needs all resident
#define SETUP0 120        // transpose blocks [0,120), setup [120,244)
#define BIN0   244        // bin blocks [244, 294); 294,295 idle in phase0/1
#define NBIN   50
#define BINPX  4608       // 50*4608 = 230400 exactly

// ---------------- device scratch (zero at first entry; restored each run) ----
__device__ __align__(16) float g_feats_t[IN_HW*IN_HW*FCH];   // [y][x][c]
__device__ __align__(16) float g_mn[NCLS*FCH];
__device__ float g_iszero[NCLS];
__device__ int   g_hist[NCLS];          // counts (reset in finalize)
__device__ int   g_cursor[NCLS];        // reservation cursors (reset in finalize)
__device__ int   g_binned[NPIX];        // pix | (cls<<18), class-contiguous
__device__ __align__(16) float g_sum[NCLS*FCH];
__device__ __align__(16) float g_wx[NCLS*FCH];
__device__ float g_wsum[NCLS];

__device__ int      g_bar_count = 0;    // self-resetting
__device__ unsigned g_bar_gen   = 0;    // monotonic across replays

__constant__ float c_frac[4] = {0.625f, 0.875f, 0.125f, 0.375f};

// Grid barrier: RED arrive, block 0 polls + flips generation.
// SCAN=true: block 0 does the 124-class exclusive scan inside the critical section.
template<bool SCAN>
__device__ __forceinline__ void gsync(int* h) {
    const int t = threadIdx.x;
    __syncthreads();
    __threadfence();
    unsigned my = 0;
    if (t == 0) {
        my = *(volatile unsigned*)&g_bar_gen;
        atomicAdd(&g_bar_count, 1);              // return unused -> RED
    }
    if (blockIdx.x == 0) {
        if (t == 0) {
            while (*(volatile int*)&g_bar_count < GRID) __nanosleep(32);
            __threadfence();
        }
        __syncthreads();
        if (SCAN) {
            int hv = 0;
            if (t < 128) { hv = (t < NCLS) ? g_hist[t] : 0; h[t] = hv; }
            __syncthreads();
            #pragma unroll
            for (int o = 1; o < 128; o <<= 1) {
                int u = (t < 128 && t >= o) ? h[t - o] : 0;
                __syncthreads();
                if (t < 128) h[t] += u;
                __syncthreads();
            }
            if (t < NCLS) g_cursor[t] = h[t] - hv;   // exclusive prefix
        }
        __threadfence();
        __syncthreads();
        if (t == 0) {
            g_bar_count = 0;
            __threadfence();
            *(volatile unsigned*)&g_bar_gen = my + 1;
        }
    } else {
        if (t == 0) {
            while (*(volatile unsigned*)&g_bar_gen == my) __nanosleep(32);
            __threadfence();
        }
    }
    __syncthreads();
}

__global__ void __launch_bounds__(256, 2)
k_mega(const float* __restrict__ feats, const float* __restrict__ memory,
       const int* __restrict__ seg, float* __restrict__ out) {
    __shared__ float tile[FCH*61];   // 15616B: transpose half-row (60 cols, pad 61)
    __shared__ int   h[128];         // bin hist/bases; block0: scan scratch
    const int b = blockIdx.x;
    const int t = threadIdx.x;

    // ---- phase 0: transpose(120) | setup(124) | per-block histogram(50) ----
    if (b < SETUP0) {
        const int y = b;
        #pragma unroll
        for (int hx = 0; hx < 2; ++hx) {
            const int xh = hx * 60;
            for (int i = t; i < FCH*60; i += 256) {
                int c = i / 60, x = i - c*60;
                tile[c*61 + x] = feats[c*IN_HW*IN_HW + y*IN_HW + xh + x];
            }
            __syncthreads();
            for (int i = t; i < 60*FCH; i += 256) {
                int x = i >> 6, c = i & 63;
                g_feats_t[(y*IN_HW + xh + x)*FCH + c] = tile[c*61 + x];
            }
            __syncthreads();
        }
    } else if (b < BIN0) {
        const int c = b - SETUP0;
        if (t < 32) {                    // warp 0: normalize memory row
            float v0 = memory[c*FCH + t];
            float v1 = memory[c*FCH + t + 32];
            float s = v0*v0 + v1*v1;
            #pragma unroll
            for (int o = 16; o; o >>= 1) s += __shfl_xor_sync(0xffffffffu, s, o);
            float inv = 1.0f / fmaxf(sqrtf(s), EPS_F);
            g_mn[c*FCH + t]      = v0 * inv;
            g_mn[c*FCH + t + 32] = v1 * inv;
            if (t == 0) {
                g_iszero[c] = (s == 0.0f) ? 1.0f : 0.0f;
                g_wsum[c] = 0.0f;
            }
        } else if (t < 96) {             // disjoint threads: zero accumulators
            g_sum[c*FCH + (t - 32)] = 0.0f;
            g_wx [c*FCH + (t - 32)] = 0.0f;
        }
    } else if (b < BIN0 + NBIN) {
        if (t < 128) h[t] = 0;
        __syncthreads();
        const int base = (b - BIN0) * BINPX;
        for (int i = t; i < BINPX; i += 256)
            atomicAdd(&h[seg[base + i]], 1);
        __syncthreads();
        if (t < NCLS && h[t]) atomicAdd(&g_hist[t], h[t]);   // RED (no return)
    }
    gsync<true>(h);     // barrier + class scan (g_cursor = exclusive prefix)

    // ---- phase 1: scatter (bin blocks reserve ranges, fill via smem cursors)
    if (b >= BIN0 && b < BIN0 + NBIN) {
        if (t < NCLS) {
            int cnt = h[t];
            h[t] = cnt ? atomicAdd(&g_cursor[t], cnt) : 0;   // block's base
        }
        __syncthreads();
        const int base = (b - BIN0) * BINPX;
        for (int i = t; i < BINPX; i += 256) {
            int pix = base + i;
            int c = seg[pix];
            int slot = atomicAdd(&h[c], 1);                  // smem cursor
            g_binned[slot] = pix | (c << 18);
        }
    }
    gsync<false>(h);

    // ---- phase 2: main (8 lanes/pixel, 8 pixels/warp-iter = pair per subgroup)
    {
        const int lane = t & 31;
        const int sub  = lane >> 3;
        const int sl   = lane & 7;
        const int gw   = (b*256 + t) >> 5;
        const int nw   = (GRID*256) >> 5;
        const int chunk = (NPIX + nw - 1) / nw;
        const int j0   = gw * chunk;
        const int jend = min(j0 + chunk, NPIX);

        if (j0 < jend) {
            const float4* __restrict__ ft4 = (const float4*)g_feats_t;
            const float4* __restrict__ mn4 = (const float4*)g_mn;

            float4 sA = {0,0,0,0}, sB = {0,0,0,0}, wA = {0,0,0,0}, wB = {0,0,0,0};
            float  aw = 0.f;
            float4 mA = {0,0,0,0}, mB = {0,0,0,0};
            int cur = -1;

            for (int j = j0; j < jend; j += 8) {
                const int idx0 = j + sub;
                const int idx1 = j + 4 + sub;
                const bool valid0 = idx0 < jend;
                const bool valid1 = idx1 < jend;
                const int packed0 = g_binned[valid0 ? idx0 : (jend - 1)];
                const int packed1 = g_binned[valid1 ? idx1 : (jend - 1)];
                const int cls0 = packed0 >> 18;
                const int cls1 = packed1 >> 18;
                const int pix0 = packed0 & 0x3FFFF;
                const int pix1 = packed1 & 0x3FFFF;

                // geometry for both pixels
                const int oy0 = pix0 / 480, ox0 = pix0 - oy0*480;
                const int oy1 = pix1 / 480, ox1 = pix1 - oy1*480;
                const int iy0a = (oy0 >> 2) + ((oy0 >> 1) & 1) - 1;
                const int ix0a = (ox0 >> 2) + ((ox0 >> 1) & 1) - 1;
                const int iy0b = (oy1 >> 2) + ((oy1 >> 1) & 1) - 1;
                const int ix0b = (ox1 >> 2) + ((ox1 >> 1) & 1) - 1;
                const float fy0 = c_frac[oy0 & 3], fx0 = c_frac[ox0 & 3];
                const float fy1 = c_frac[oy1 & 3], fx1 = c_frac[ox1 & 3];
                const int y0a = max(iy0a, 0), y1a = min(iy0a + 1, IN_HW - 1);
                const int x0a = max(ix0a, 0), x1a = min(ix0a + 1, IN_HW - 1);
                const int y0b = max(iy0b, 0), y1b = min(iy0b + 1, IN_HW - 1);
                const int x0b = max(ix0b, 0), x1b = min(ix0b + 1, IN_HW - 1);
                const float p11 = fy0 * fx0, p10 = fy0 - p11, p01 = fx0 - p11,
                            p00 = 1.0f - fy0 - fx0 + p11;
                const float q11 = fy1 * fx1, q10 = fy1 - q11, q01 = fx1 - q11,
                            q00 = 1.0f - fy1 - fx1 + q11;

                const int rA0 = (y0a*IN_HW + x0a)*16, rB0 = (y0a*IN_HW + x1a)*16;
                const int rC0 = (y1a*IN_HW + x0a)*16, rD0 = (y1a*IN_HW + x1a)*16;
                const int rA1 = (y0b*IN_HW + x0b)*16, rB1 = (y0b*IN_HW + x1b)*16;
                const int rC1 = (y1b*IN_HW + x0b)*16, rD1 = (y1b*IN_HW + x1b)*16;

                // issue all 16 tap loads up front (MLP 16)
                const float4 a0 = ft4[rA0 + sl],     b0 = ft4[rB0 + sl];
                const float4 c0 = ft4[rC0 + sl],     d0 = ft4[rD0 + sl];
                const float4 a1 = ft4[rA0 + 8 + sl], b1 = ft4[rB0 + 8 + sl];
                const float4 c1 = ft4[rC0 + 8 + sl], d1 = ft4[rD0 + 8 + sl];
                const float4 e0 = ft4[rA1 + sl],     f0 = ft4[rB1 + sl];
                const float4 g0 = ft4[rC1 + sl],     k0 = ft4[rD1 + sl];
                const float4 e1 = ft4[rA1 + 8 + sl], f1 = ft4[rB1 + 8 + sl];
                const float4 g1 = ft4[rC1 + 8 + sl], k1 = ft4[rD1 + 8 + sl];

                // interp both pixels (independent FMA trees)
                float4 v0, v1, u0, u1;
                v0.x = p00*a0.x + p01*b0.x + p10*c0.x + p11*d0.x;
                v0.y = p00*a0.y + p01*b0.y + p10*c0.y + p11*d0.y;
                v0.z = p00*a0.z + p01*b0.z + p10*c0.z + p11*d0.z;
                v0.w = p00*a0.w + p01*b0.w + p10*c0.w + p11*d0.w;
                v1.x = p00*a1.x + p01*b1.x + p10*c1.x + p11*d1.x;
                v1.y = p00*a1.y + p01*b1.y + p10*c1.y + p11*d1.y;
                v1.z = p00*a1.z + p01*b1.z + p10*c1.z + p11*d1.z;
                v1.w = p00*a1.w + p01*b1.w + p10*c1.w + p11*d1.w;
                u0.x = q00*e0.x + q01*f0.x + q10*g0.x + q11*k0.x;
                u0.y = q00*e0.y + q01*f0.y + q10*g0.y + q11*k0.y;
                u0.z = q00*e0.z + q01*f0.z + q10*g0.z + q11*k0.z;
                u0.w = q00*e0.w + q01*f0.w + q10*g0.w + q11*k0.w;
                u1.x = q00*e1.x + q01*f1.x + q10*g1.x + q11*k1.x;
                u1.y = q00*e1.y + q01*f1.y + q10*g1.y + q11*k1.y;
                u1.z = q00*e1.z + q01*f1.z + q10*g1.z + q11*k1.z;
                u1.w = q00*e1.w + q01*f1.w + q10*g1.w + q11*k1.w;

                const bool same = (cls0 == cur) & (cls1 == cur);
                if (__all_sync(0xffffffffu, same)) {
                    // -------- fast path: both pixels in current class --------
                    float nsq0 = v0.x*v0.x + v0.y*v0.y + v0.z*v0.z + v0.w*v0.w
                               + v1.x*v1.x + v1.y*v1.y + v1.z*v1.z + v1.w*v1.w;
                    float dt0  = v0.x*mA.x + v0.y*mA.y + v0.z*mA.z + v0.w*mA.w
                               + v1.x*mB.x + v1.y*mB.y + v1.z*mB.z + v1.w*mB.w;
                    float nsq1 = u0.x*u0.x + u0.y*u0.y + u0.z*u0.z + u0.w*u0.w
                               + u1.x*u1.x + u1.y*u1.y + u1.z*u1.z + u1.w*u1.w;
                    float dt1  = u0.x*mA.x + u0.y*mA.y + u0.z*mA.z + u0.w*mA.w
                               + u1.x*mB.x + u1.y*mB.y + u1.z*mB.z + u1.w*mB.w;
                    #pragma unroll
                    for (int o = 4; o; o >>= 1) {     // 4 interleaved chains
                        nsq0 += __shfl_xor_sync(0xffffffffu, nsq0, o);
                        dt0  += __shfl_xor_sync(0xffffffffu, dt0,  o);
                        nsq1 += __shfl_xor_sync(0xffffffffu, nsq1, o);
                        dt1  += __shfl_xor_sync(0xffffffffu, dt1,  o);
                    }
                    const float wg0 = 1.0f - dt0 * rsqrtf(fmaxf(nsq0, 1e-16f));
                    const float wg1 = 1.0f - dt1 * rsqrtf(fmaxf(nsq1, 1e-16f));
                    const float vv0 = valid0 ? 1.0f : 0.0f;
                    const float vv1 = valid1 ? 1.0f : 0.0f;
                    const float gg0 = valid0 ? wg0 : 0.0f;
                    const float gg1 = valid1 ? wg1 : 0.0f;

                    sA.x = fmaf(vv0,v0.x,fmaf(vv1,u0.x,sA.x));
                    sA.y = fmaf(vv0,v0.y,fmaf(vv1,u0.y,sA.y));
                    sA.z = fmaf(vv0,v0.z,fmaf(vv1,u0.z,sA.z));
                    sA.w = fmaf(vv0,v0.w,fmaf(vv1,u0.w,sA.w));
                    sB.x = fmaf(vv0,v1.x,fmaf(vv1,u1.x,sB.x));
                    sB.y = fmaf(vv0,v1.y,fmaf(vv1,u1.y,sB.y));
                    sB.z = fmaf(vv0,v1.z,fmaf(vv1,u1.z,sB.z));
                    sB.w = fmaf(vv0,v1.w,fmaf(vv1,u1.w,sB.w));
                    wA.x = fmaf(gg0,v0.x,fmaf(gg1,u0.x,wA.x));
                    wA.y = fmaf(gg0,v0.y,fmaf(gg1,u0.y,wA.y));
                    wA.z = fmaf(gg0,v0.z,fmaf(gg1,u0.z,wA.z));
                    wA.w = fmaf(gg0,v0.w,fmaf(gg1,u0.w,wA.w));
                    wB.x = fmaf(gg0,v1.x,fmaf(gg1,u1.x,wB.x));
                    wB.y = fmaf(gg0,v1.y,fmaf(gg1,u1.y,wB.y));
                    wB.z = fmaf(gg0,v1.z,fmaf(gg1,u1.z,wB.z));
                    wB.w = fmaf(gg0,v1.w,fmaf(gg1,u1.w,wB.w));
                    aw += gg0 + gg1;
                } else {
                    // -------- slow path: class boundary (rare) --------
                    // pixel 0
                    if (cls0 != cur) {
                        if (cur >= 0) {
                            atomicAdd((float4*)&g_sum[cur*FCH + 4*sl],      sA);
                            atomicAdd((float4*)&g_sum[cur*FCH + 32 + 4*sl], sB);
                            atomicAdd((float4*)&g_wx [cur*FCH + 4*sl],      wA);
                            atomicAdd((float4*)&g_wx [cur*FCH + 32 + 4*sl], wB);
                            if (sl == 0) atomicAdd(&g_wsum[cur], aw);
                        }
                        sA = make_float4(0,0,0,0); sB = make_float4(0,0,0,0);
                        wA = make_float4(0,0,0,0); wB = make_float4(0,0,0,0);
                        aw = 0.f;
                        cur = cls0;
                        mA = mn4[cls0*16 + sl];
                        mB = mn4[cls0*16 + 8 + sl];
                    }
                    {
                        float nsq = v0.x*v0.x + v0.y*v0.y + v0.z*v0.z + v0.w*v0.w
                                  + v1.x*v1.x + v1.y*v1.y + v1.z*v1.z + v1.w*v1.w;
                        float dt  = v0.x*mA.x + v0.y*mA.y + v0.z*mA.z + v0.w*mA.w
                                  + v1.x*mB.x + v1.y*mB.y + v1.z*mB.z + v1.w*mB.w;
                        #pragma unroll
                        for (int o = 4; o; o >>= 1) {
                            nsq += __shfl_xor_sync(0xffffffffu, nsq, o);
                            dt  += __shfl_xor_sync(0xffffffffu, dt,  o);
                        }
                        const float wg = 1.0f - dt * rsqrtf(fmaxf(nsq, 1e-16f));
                        const float vv = valid0 ? 1.0f : 0.0f;
                        const float gg = valid0 ? wg : 0.0f;
                        sA.x = fmaf(vv,v0.x,sA.x); sA.y = fmaf(vv,v0.y,sA.y);
                        sA.z = fmaf(vv,v0.z,sA.z); sA.w = fmaf(vv,v0.w,sA.w);
                        sB.x = fmaf(vv,v1.x,sB.x); sB.y = fmaf(vv,v1.y,sB.y);
                        sB.z = fmaf(vv,v1.z,sB.z); sB.w = fmaf(vv,v1.w,sB.w);
                        wA.x = fmaf(gg,v0.x,wA.x); wA.y = fmaf(gg,v0.y,wA.y);
                        wA.z = fmaf(gg,v0.z,wA.z); wA.w = fmaf(gg,v0.w,wA.w);
                        wB.x = fmaf(gg,v1.x,wB.x); wB.y = fmaf(gg,v1.y,wB.y);
                        wB.z = fmaf(gg,v1.z,wB.z); wB.w = fmaf(gg,v1.w,wB.w);
                        aw += gg;
                    }
                    // pixel 1
                    if (cls1 != cur) {
                        if (cur >= 0) {
                            atomicAdd((float4*)&g_sum[cur*FCH + 4*sl],      sA);
                            atomicAdd((float4*)&g_sum[cur*FCH + 32 + 4*sl], sB);
                            atomicAdd((float4*)&g_wx [cur*FCH + 4*sl],      wA);
                            atomicAdd((float4*)&g_wx [cur*FCH + 32 + 4*sl], wB);
                            if (sl == 0) atomicAdd(&g_wsum[cur], aw);
                        }
                        sA = make_float4(0,0,0,0); sB = make_float4(0,0,0,0);
                        wA = make_float4(0,0,0,0); wB = make_float4(0,0,0,0);
                        aw = 0.f;
                        cur = cls1;
                        mA = mn4[cls1*16 + sl];
                        mB = mn4[cls1*16 + 8 + sl];
                    }
                    {
                        float nsq = u0.x*u0.x + u0.y*u0.y + u0.z*u0.z + u0.w*u0.w
                                  + u1.x*u1.x + u1.y*u1.y + u1.z*u1.z + u1.w*u1.w;
                        float dt  = u0.x*mA.x + u0.y*mA.y + u0.z*mA.z + u0.w*mA.w
                                  + u1.x*mB.x + u1.y*mB.y + u1.z*mB.z + u1.w*mB.w;
                        #pragma unroll
                        for (int o = 4; o; o >>= 1) {
                            nsq += __shfl_xor_sync(0xffffffffu, nsq, o);
                            dt  += __shfl_xor_sync(0xffffffffu, dt,  o);
                        }
                        const float wg = 1.0f - dt * rsqrtf(fmaxf(nsq, 1e-16f));
                        const float vv = valid1 ? 1.0f : 0.0f;
                        const float gg = valid1 ? wg : 0.0f;
                        sA.x = fmaf(vv,u0.x,sA.x); sA.y = fmaf(vv,u0.y,sA.y);
                        sA.z = fmaf(vv,u0.z,sA.z); sA.w = fmaf(vv,u0.w,sA.w);
                        sB.x = fmaf(vv,u1.x,sB.x); sB.y = fmaf(vv,u1.y,sB.y);
                        sB.z = fmaf(vv,u1.z,sB.z); sB.w = fmaf(vv,u1.w,sB.w);
                        wA.x = fmaf(gg,u0.x,wA.x); wA.y = fmaf(gg,u0.y,wA.y);
                        wA.z = fmaf(gg,u0.z,wA.z); wA.w = fmaf(gg,u0.w,wA.w);
                        wB.x = fmaf(gg,u1.x,wB.x); wB.y = fmaf(gg,u1.y,wB.y);
                        wB.z = fmaf(gg,u1.z,wB.z); wB.w = fmaf(gg,u1.w,wB.w);
                        aw += gg;
                    }
                }
            }

            if (cur >= 0) {
                atomicAdd((float4*)&g_sum[cur*FCH + 4*sl],      sA);
                atomicAdd((float4*)&g_sum[cur*FCH + 32 + 4*sl], sB);
                atomicAdd((float4*)&g_wx [cur*FCH + 4*sl],      wA);
                atomicAdd((float4*)&g_wx [cur*FCH + 32 + 4*sl], wB);
                if (sl == 0) atomicAdd(&g_wsum[cur], aw);
            }
        }
    }
    gsync<false>(h);

    // ---- phase 3: finalize + restore scratch for next replay ----
    if (b < NCLS) {
        const int c = b;
        if (t < FCH) {
            const int cnt = g_hist[c];
            const float memv = memory[c*FCH + t];
            float res = memv;
            if (cnt > 0) {
                if (g_iszero[c] != 0.0f) {
                    res = g_sum[c*FCH + t] / fmaxf((float)cnt, 1.0f);
                } else {
                    const float ws = g_wsum[c];
                    const float weighted = g_wx[c*FCH + t] / ((ws != 0.0f) ? ws : 1.0f);
                    res = 0.9f * memv + 0.1f * weighted;
                }
            }
            out[c*FCH + t] = res;
        }
        __syncthreads();
        if (t == 0) { g_hist[c] = 0; g_cursor[c] = 0; }
    }
}

// ---------------- launch ----------------
extern "C" void kernel_launch(void* const* d_in, const int* in_sizes, int n_in,
                              void* d_out, int out_size) {
    const float* feats  = (const float*)d_in[0];
    const float* memory = (const float*)d_in[1];
    const int*   seg    = (const int*)  d_in[2];
    float* out = (float*)d_out;
    k_mega<<<GRID, 256>>>(feats, memory, seg, out);
}